// round 9
// baseline (speedup 1.0000x reference)
#include <cuda_runtime.h>

#define T_STEPS 2048
#define BATCH   256
#define DIN     128
#define NG      16      // scratch layout k = u*4 + g
#define RDEPTH  4

// Scratch: x-part projections (+bias+theta folded), layout [t][b][u*4+g]
// Over-allocated by RDEPTH steps so the recurrence prefetch needs no bounds check.
__device__ float g_xproj[(T_STEPS + RDEPTH) * BATCH * NG];

// ---------------------------------------------------------------------------
// Kernel 1: fused 4-gate projection (R7 version: 132-stride, float4 LDS —
// that layout is conflict-free for LDS.128; the 133/scalar variant regressed)
// ---------------------------------------------------------------------------
#define TILE_ROWS    64
#define PROJ_THREADS 256

__global__ __launch_bounds__(PROJ_THREADS)
void proj_kernel(const float* __restrict__ x,
                 const float* __restrict__ Wf, const float* __restrict__ bf, const float* __restrict__ thf,
                 const float* __restrict__ Wi, const float* __restrict__ bi, const float* __restrict__ thi,
                 const float* __restrict__ Wu, const float* __restrict__ bu, const float* __restrict__ thu,
                 const float* __restrict__ Wo, const float* __restrict__ bo, const float* __restrict__ tho)
{
    __shared__ float xs[TILE_ROWS][132];
    __shared__ float ws[DIN][NG];          // ws[j][u*4+g]
    __shared__ float bt[NG];

    const int tid = threadIdx.x;
    const long rowBase = (long)blockIdx.x * TILE_ROWS;

    const float4* x4 = (const float4*)x + rowBase * (DIN / 4);
    #pragma unroll
    for (int i = tid; i < TILE_ROWS * (DIN / 4); i += PROJ_THREADS) {
        float4 v = x4[i];
        int row = i >> 5;
        int c4  = i & 31;
        *(float4*)&xs[row][c4 * 4] = v;
    }
    // stage W transposed: k = u*4 + g
    for (int i = tid; i < DIN * NG; i += PROJ_THREADS) {
        int j = i >> 4, k = i & 15;
        int u = k >> 2, g = k & 3;
        const float* W = (g == 0) ? Wf : (g == 1) ? Wi : (g == 2) ? Wu : Wo;
        ws[j][k] = W[j * 4 + u];
    }
    if (tid < NG) {
        int u = tid >> 2, g = tid & 3;
        const float* b  = (g == 0) ? bf  : (g == 1) ? bi  : (g == 2) ? bu  : bo;
        const float* th = (g == 0) ? thf : (g == 1) ? thi : (g == 2) ? thu : tho;
        bt[tid] = b[u] + th[u];
    }
    __syncthreads();

    const int r  = tid & (TILE_ROWS - 1);
    const int kg = tid >> 6;
    float a0 = 0.f, a1 = 0.f, a2 = 0.f, a3 = 0.f;

    #pragma unroll
    for (int jj = 0; jj < DIN / 4; jj++) {
        float4 xv = *(const float4*)&xs[r][jj * 4];
        float4 w0 = *(const float4*)&ws[jj * 4 + 0][kg * 4];
        float4 w1 = *(const float4*)&ws[jj * 4 + 1][kg * 4];
        float4 w2 = *(const float4*)&ws[jj * 4 + 2][kg * 4];
        float4 w3 = *(const float4*)&ws[jj * 4 + 3][kg * 4];
        a0 = fmaf(xv.x, w0.x, fmaf(xv.y, w1.x, fmaf(xv.z, w2.x, fmaf(xv.w, w3.x, a0))));
        a1 = fmaf(xv.x, w0.y, fmaf(xv.y, w1.y, fmaf(xv.z, w2.y, fmaf(xv.w, w3.y, a1))));
        a2 = fmaf(xv.x, w0.z, fmaf(xv.y, w1.z, fmaf(xv.z, w2.z, fmaf(xv.w, w3.z, a2))));
        a3 = fmaf(xv.x, w0.w, fmaf(xv.y, w1.w, fmaf(xv.z, w2.w, fmaf(xv.w, w3.w, a3))));
    }
    float4 o;
    o.x = a0 + bt[kg * 4 + 0];
    o.y = a1 + bt[kg * 4 + 1];
    o.z = a2 + bt[kg * 4 + 2];
    o.w = a3 + bt[kg * 4 + 3];
    *(float4*)&g_xproj[(rowBase + r) * NG + kg * 4] = o;
}

// ---------------------------------------------------------------------------
// Kernel 2: recurrence; 4 lanes/element; single shfl stage (cos transpose),
// then fully redundant per-lane state (all lanes hold identical c[4], h[4]).
// ---------------------------------------------------------------------------
// HW tanh (MUFU.TANH)
__device__ __forceinline__ float tanh_a(float x) {
    float y;
    asm("tanh.approx.f32 %0, %1;" : "=f"(y) : "f"(x));
    return y;
}
// sigmoid via HW tanh (2 FMA + 1 MUFU)
__device__ __forceinline__ float sig_t(float x) {
    return fmaf(0.5f, tanh_a(0.5f * x), 0.5f);
}
// sigmoid on [-1,1] via odd Taylor poly (FMA pipe only) — balances MUFU pressure
__device__ __forceinline__ float sigp(float xv) {
    float x2 = xv * xv;
    float t = fmaf(x2, 2.135765e-5f, -2.1081349e-4f);
    t = fmaf(x2, t, 2.0833333e-3f);
    t = fmaf(x2, t, -2.0833333e-2f);
    t = fmaf(x2, t, 0.25f);
    return fmaf(xv, t, 0.5f);
}

#define FULLMASK 0xffffffffu

__global__ __launch_bounds__(32)
void recur_kernel(const float* __restrict__ Wf, const float* __restrict__ Wi,
                  const float* __restrict__ Wu, const float* __restrict__ Wo,
                  float* __restrict__ out)
{
    const int lane = threadIdx.x;
    const int u    = lane & 3;                       // hidden unit owned by this lane
    const int b    = blockIdx.x * 8 + (lane >> 2);   // batch element of this 4-lane group

    // Whl[m][g] = W_gate_g[(128+m)*4 + u] : into (gate g, unit u)
    float Whl[4][4];
    #pragma unroll
    for (int m = 0; m < 4; m++) {
        Whl[m][0] = Wf[(128 + m) * 4 + u];
        Whl[m][1] = Wi[(128 + m) * 4 + u];
        Whl[m][2] = Wu[(128 + m) * 4 + u];
        Whl[m][3] = Wo[(128 + m) * 4 + u];
    }

    // redundant full state on every lane (bitwise identical across the quad)
    float h0 = 0.f, h1 = 0.f, h2 = 0.f, h3 = 0.f;
    float c0 = 0.f, c1 = 0.f, c2 = 0.f, c3 = 0.f;

    const float4* xp = (const float4*)g_xproj + ((size_t)b * 4 + u);
    float4 buf[RDEPTH];
    #pragma unroll
    for (int d = 0; d < RDEPTH; d++)
        buf[d] = xp[(size_t)d * (BATCH * 4)];

    #pragma unroll 2
    for (int t = 0; t < T_STEPS; t++) {
        const int slot = t & (RDEPTH - 1);
        float4 zx = buf[slot];
        buf[slot] = xp[(size_t)(t + RDEPTH) * (BATCH * 4)];  // over-allocated: no bound check

        // distributed part: z & cos for THIS lane's unit, all 4 gates
        float a, bb;
        a  = fmaf(h1, Whl[1][0], fmaf(h0, Whl[0][0], zx.x));
        bb = fmaf(h3, Whl[3][0], h2 * Whl[2][0]);
        float qf = __cosf(a + bb);
        a  = fmaf(h1, Whl[1][1], fmaf(h0, Whl[0][1], zx.y));
        bb = fmaf(h3, Whl[3][1], h2 * Whl[2][1]);
        float qi = __cosf(a + bb);
        a  = fmaf(h1, Whl[1][2], fmaf(h0, Whl[0][2], zx.z));
        bb = fmaf(h3, Whl[3][2], h2 * Whl[2][2]);
        float qu = __cosf(a + bb);
        a  = fmaf(h1, Whl[1][3], fmaf(h0, Whl[0][3], zx.w));
        bb = fmaf(h3, Whl[3][3], h2 * Whl[2][3]);
        float qo = __cosf(a + bb);

        // ONE parallel shfl stage: transpose so every lane holds all units' cos
        float f0 = __shfl_sync(FULLMASK, qf, 0, 4);
        float f1 = __shfl_sync(FULLMASK, qf, 1, 4);
        float f2 = __shfl_sync(FULLMASK, qf, 2, 4);
        float f3 = __shfl_sync(FULLMASK, qf, 3, 4);
        float i0 = __shfl_sync(FULLMASK, qi, 0, 4);
        float i1 = __shfl_sync(FULLMASK, qi, 1, 4);
        float i2 = __shfl_sync(FULLMASK, qi, 2, 4);
        float i3 = __shfl_sync(FULLMASK, qi, 3, 4);
        float g0 = __shfl_sync(FULLMASK, qu, 0, 4);
        float g1 = __shfl_sync(FULLMASK, qu, 1, 4);
        float g2 = __shfl_sync(FULLMASK, qu, 2, 4);
        float g3 = __shfl_sync(FULLMASK, qu, 3, 4);
        float o0 = __shfl_sync(FULLMASK, qo, 0, 4);
        float o1 = __shfl_sync(FULLMASK, qo, 1, 4);
        float o2 = __shfl_sync(FULLMASK, qo, 2, 4);
        float o3 = __shfl_sync(FULLMASK, qo, 3, 4);

        // local cumprod per gate (exactly the reference's serial order)
        f1 *= f0;  f2 *= f1;  f3 *= f2;
        i1 *= i0;  i2 *= i1;  i3 *= i2;
        g1 *= g0;  g2 *= g1;  g3 *= g2;
        o1 *= o0;  o2 *= o1;  o3 *= o2;

        // activations (f,i via MUFU-sigmoid; o via FMA-pipe poly; g via tanh)
        f0 = sig_t(f0);  f1 = sig_t(f1);  f2 = sig_t(f2);  f3 = sig_t(f3);
        i0 = sig_t(i0);  i1 = sig_t(i1);  i2 = sig_t(i2);  i3 = sig_t(i3);
        g0 = tanh_a(g0); g1 = tanh_a(g1); g2 = tanh_a(g2); g3 = tanh_a(g3);
        o0 = sigp(o0);   o1 = sigp(o1);   o2 = sigp(o2);   o3 = sigp(o3);

        // redundant cell + hidden update on every lane
        c0 = fmaf(f0, c0, i0 * g0);
        c1 = fmaf(f1, c1, i1 * g1);
        c2 = fmaf(f2, c2, i2 * g2);
        c3 = fmaf(f3, c3, i3 * g3);
        h0 = o0 * tanh_a(c0);
        h1 = o1 * tanh_a(c1);
        h2 = o2 * tanh_a(c2);
        h3 = o3 * tanh_a(c3);

        // each lane stores its own unit (32 contiguous floats per warp)
        float hu = (u == 0) ? h0 : (u == 1) ? h1 : (u == 2) ? h2 : h3;
        out[((size_t)t * BATCH + b) * 4 + u] = hu;
    }

    // hx, cx appended after outputs
    float hu = (u == 0) ? h0 : (u == 1) ? h1 : (u == 2) ? h2 : h3;
    float cu = (u == 0) ? c0 : (u == 1) ? c1 : (u == 2) ? c2 : c3;
    out[(size_t)T_STEPS * BATCH * 4 + (size_t)b * 4 + u]                     = hu;
    out[(size_t)T_STEPS * BATCH * 4 + (size_t)BATCH * 4 + (size_t)b * 4 + u] = cu;
}

// ---------------------------------------------------------------------------
extern "C" void kernel_launch(void* const* d_in, const int* in_sizes, int n_in,
                              void* d_out, int out_size)
{
    (void)in_sizes; (void)n_in; (void)out_size;
    const float* x   = (const float*)d_in[0];
    const float* Wf  = (const float*)d_in[1];
    const float* bf  = (const float*)d_in[2];
    const float* thf = (const float*)d_in[3];
    const float* Wi  = (const float*)d_in[4];
    const float* bi  = (const float*)d_in[5];
    const float* thi = (const float*)d_in[6];
    const float* Wu  = (const float*)d_in[7];
    const float* bu  = (const float*)d_in[8];
    const float* thu = (const float*)d_in[9];
    const float* Wo  = (const float*)d_in[10];
    const float* bo  = (const float*)d_in[11];
    const float* tho = (const float*)d_in[12];
    float* out = (float*)d_out;

    proj_kernel<<<(T_STEPS * BATCH) / TILE_ROWS, PROJ_THREADS>>>(
        x, Wf, bf, thf, Wi, bi, thi, Wu, bu, thu, Wo, bo, tho);
    recur_kernel<<<BATCH / 8, 32>>>(Wf, Wi, Wu, Wo, out);
}

// round 10
// speedup vs baseline: 2.4702x; 2.4702x over previous
#include <cuda_runtime.h>

#define T_STEPS 2048
#define BATCH   256
#define DIN     128
#define NG      16      // scratch layout k = u*4 + g
#define RDEPTH  4

// Scratch: x-part projections (+bias+theta folded), layout [t][b][u*4+g]
// Over-allocated by RDEPTH steps so the recurrence prefetch needs no bounds check.
__device__ float g_xproj[(T_STEPS + RDEPTH) * BATCH * NG];

// ---------------------------------------------------------------------------
// Kernel 1: fused 4-gate projection (R7/541us version: 132-stride float4 LDS)
// ---------------------------------------------------------------------------
#define TILE_ROWS    64
#define PROJ_THREADS 256

__global__ __launch_bounds__(PROJ_THREADS)
void proj_kernel(const float* __restrict__ x,
                 const float* __restrict__ Wf, const float* __restrict__ bf, const float* __restrict__ thf,
                 const float* __restrict__ Wi, const float* __restrict__ bi, const float* __restrict__ thi,
                 const float* __restrict__ Wu, const float* __restrict__ bu, const float* __restrict__ thu,
                 const float* __restrict__ Wo, const float* __restrict__ bo, const float* __restrict__ tho)
{
    __shared__ float xs[TILE_ROWS][132];
    __shared__ float ws[DIN][NG];          // ws[j][u*4+g]
    __shared__ float bt[NG];

    const int tid = threadIdx.x;
    const long rowBase = (long)blockIdx.x * TILE_ROWS;

    const float4* x4 = (const float4*)x + rowBase * (DIN / 4);
    #pragma unroll
    for (int i = tid; i < TILE_ROWS * (DIN / 4); i += PROJ_THREADS) {
        float4 v = x4[i];
        int row = i >> 5;
        int c4  = i & 31;
        *(float4*)&xs[row][c4 * 4] = v;
    }
    // stage W transposed: k = u*4 + g
    for (int i = tid; i < DIN * NG; i += PROJ_THREADS) {
        int j = i >> 4, k = i & 15;
        int u = k >> 2, g = k & 3;
        const float* W = (g == 0) ? Wf : (g == 1) ? Wi : (g == 2) ? Wu : Wo;
        ws[j][k] = W[j * 4 + u];
    }
    if (tid < NG) {
        int u = tid >> 2, g = tid & 3;
        const float* b  = (g == 0) ? bf  : (g == 1) ? bi  : (g == 2) ? bu  : bo;
        const float* th = (g == 0) ? thf : (g == 1) ? thi : (g == 2) ? thu : tho;
        bt[tid] = b[u] + th[u];
    }
    __syncthreads();

    const int r  = tid & (TILE_ROWS - 1);
    const int kg = tid >> 6;
    float a0 = 0.f, a1 = 0.f, a2 = 0.f, a3 = 0.f;

    #pragma unroll
    for (int jj = 0; jj < DIN / 4; jj++) {
        float4 xv = *(const float4*)&xs[r][jj * 4];
        float4 w0 = *(const float4*)&ws[jj * 4 + 0][kg * 4];
        float4 w1 = *(const float4*)&ws[jj * 4 + 1][kg * 4];
        float4 w2 = *(const float4*)&ws[jj * 4 + 2][kg * 4];
        float4 w3 = *(const float4*)&ws[jj * 4 + 3][kg * 4];
        a0 = fmaf(xv.x, w0.x, fmaf(xv.y, w1.x, fmaf(xv.z, w2.x, fmaf(xv.w, w3.x, a0))));
        a1 = fmaf(xv.x, w0.y, fmaf(xv.y, w1.y, fmaf(xv.z, w2.y, fmaf(xv.w, w3.y, a1))));
        a2 = fmaf(xv.x, w0.z, fmaf(xv.y, w1.z, fmaf(xv.z, w2.z, fmaf(xv.w, w3.z, a2))));
        a3 = fmaf(xv.x, w0.w, fmaf(xv.y, w1.w, fmaf(xv.z, w2.w, fmaf(xv.w, w3.w, a3))));
    }
    float4 o;
    o.x = a0 + bt[kg * 4 + 0];
    o.y = a1 + bt[kg * 4 + 1];
    o.z = a2 + bt[kg * 4 + 2];
    o.w = a3 + bt[kg * 4 + 3];
    *(float4*)&g_xproj[(rowBase + r) * NG + kg * 4] = o;
}

// ---------------------------------------------------------------------------
// Kernel 2: recurrence; 4 lanes per batch element (lane owns hidden unit u)
// R8 structure; sigmoids on the FMA pipe (no scoreboard stage), tanh on MUFU.
// ---------------------------------------------------------------------------
// HW tanh (MUFU.TANH)
__device__ __forceinline__ float tanh_a(float x) {
    float y;
    asm("tanh.approx.f32 %0, %1;" : "=f"(y) : "f"(x));
    return y;
}
// sigmoid on [-1,1] via odd Taylor poly (err <= ~3e-6): fixed-latency FMA chain,
// no scoreboard wait -> removes a var-lat stage from the f/i/o critical paths.
__device__ __forceinline__ float sigp(float xv) {
    float x2 = xv * xv;
    float t = fmaf(x2, 2.135765e-5f, -2.1081349e-4f);
    t = fmaf(x2, t, 2.0833333e-3f);
    t = fmaf(x2, t, -2.0833333e-2f);
    t = fmaf(x2, t, 0.25f);
    return fmaf(xv, t, 0.5f);
}

#define FULLMASK 0xffffffffu

__global__ __launch_bounds__(32)
void recur_kernel(const float* __restrict__ Wf, const float* __restrict__ Wi,
                  const float* __restrict__ Wu, const float* __restrict__ Wo,
                  float* __restrict__ out)
{
    const int lane = threadIdx.x;
    const int u    = lane & 3;                       // hidden unit owned by this lane
    const int b    = blockIdx.x * 8 + (lane >> 2);   // batch element of this 4-lane group

    // Whl[m][g] = W_gate_g[(128+m)*4 + u]
    float Whl[4][4];
    #pragma unroll
    for (int m = 0; m < 4; m++) {
        Whl[m][0] = Wf[(128 + m) * 4 + u];
        Whl[m][1] = Wi[(128 + m) * 4 + u];
        Whl[m][2] = Wu[(128 + m) * 4 + u];
        Whl[m][3] = Wo[(128 + m) * 4 + u];
    }
    const bool ge1 = (u >= 1);
    const bool ge2 = (u >= 2);
    const bool ge3 = (u >= 3);

    float h0 = 0.f, h1 = 0.f, h2 = 0.f, h3 = 0.f;
    float c  = 0.f;

    const float4* xp = (const float4*)g_xproj + ((size_t)b * 4 + u);
    float4 buf[RDEPTH];
    #pragma unroll
    for (int d = 0; d < RDEPTH; d++)
        buf[d] = xp[(size_t)d * (BATCH * 4)];

    #pragma unroll 4
    for (int t = 0; t < T_STEPS; t++) {
        const int slot = t & (RDEPTH - 1);
        float4 zx = buf[slot];
        buf[slot] = xp[(size_t)(t + RDEPTH) * (BATCH * 4)];  // over-allocated: no bound check

        // z_g = zx_g + h . Whl[:,g]  (tree form) then cos
        float a, bb;
        a  = fmaf(h1, Whl[1][0], fmaf(h0, Whl[0][0], zx.x));
        bb = fmaf(h3, Whl[3][0], h2 * Whl[2][0]);
        float q0 = __cosf(a + bb);
        a  = fmaf(h1, Whl[1][1], fmaf(h0, Whl[0][1], zx.y));
        bb = fmaf(h3, Whl[3][1], h2 * Whl[2][1]);
        float q1 = __cosf(a + bb);
        a  = fmaf(h1, Whl[1][2], fmaf(h0, Whl[0][2], zx.z));
        bb = fmaf(h3, Whl[3][2], h2 * Whl[2][2]);
        float q2 = __cosf(a + bb);
        a  = fmaf(h1, Whl[1][3], fmaf(h0, Whl[0][3], zx.w));
        bb = fmaf(h3, Whl[3][3], h2 * Whl[2][3]);
        float q3 = __cosf(a + bb);

        // Prefix product across the unit quad: 3 PARALLEL index-shfls per gate
        // (single shfl wait), then a 2-level predicated multiply tree.
        {
            float s00 = __shfl_sync(FULLMASK, q0, 0, 4);
            float s01 = __shfl_sync(FULLMASK, q0, 1, 4);
            float s02 = __shfl_sync(FULLMASK, q0, 2, 4);
            float s10 = __shfl_sync(FULLMASK, q1, 0, 4);
            float s11 = __shfl_sync(FULLMASK, q1, 1, 4);
            float s12 = __shfl_sync(FULLMASK, q1, 2, 4);
            float s20 = __shfl_sync(FULLMASK, q2, 0, 4);
            float s21 = __shfl_sync(FULLMASK, q2, 1, 4);
            float s22 = __shfl_sync(FULLMASK, q2, 2, 4);
            float s30 = __shfl_sync(FULLMASK, q3, 0, 4);
            float s31 = __shfl_sync(FULLMASK, q3, 1, 4);
            float s32 = __shfl_sync(FULLMASK, q3, 2, 4);
            // 2-level tree: m = s0^{[>=1]} * s1^{[>=2]}, then P = (q*m) * s2^{[>=3]}
            float m0 = ge1 ? s00 : 1.0f; if (ge2) m0 *= s01;
            float m1 = ge1 ? s10 : 1.0f; if (ge2) m1 *= s11;
            float m2 = ge1 ? s20 : 1.0f; if (ge2) m2 *= s21;
            float m3 = ge1 ? s30 : 1.0f; if (ge2) m3 *= s31;
            q0 *= m0; if (ge3) q0 *= s02;
            q1 *= m1; if (ge3) q1 *= s12;
            q2 *= m2; if (ge3) q2 *= s22;
            q3 *= m3; if (ge3) q3 *= s32;
        }

        // activations: f,i,o on FMA pipe (no SB stage); g via MUFU tanh (overlaps)
        float f  = sigp(q0);
        float i  = sigp(q1);
        float gg = tanh_a(q2);
        float o  = sigp(q3);

        c = fmaf(f, c, i * gg);
        float hu = o * tanh_a(c);

        out[((size_t)t * BATCH + b) * 4 + u] = hu;

        // broadcast h within the 4-lane group (4 parallel shfls, one wait)
        h0 = __shfl_sync(FULLMASK, hu, 0, 4);
        h1 = __shfl_sync(FULLMASK, hu, 1, 4);
        h2 = __shfl_sync(FULLMASK, hu, 2, 4);
        h3 = __shfl_sync(FULLMASK, hu, 3, 4);
    }

    // hx, cx appended after outputs
    float hx = (u == 0) ? h0 : (u == 1) ? h1 : (u == 2) ? h2 : h3;
    out[(size_t)T_STEPS * BATCH * 4 + (size_t)b * 4 + u]                     = hx;
    out[(size_t)T_STEPS * BATCH * 4 + (size_t)BATCH * 4 + (size_t)b * 4 + u] = c;
}

// ---------------------------------------------------------------------------
extern "C" void kernel_launch(void* const* d_in, const int* in_sizes, int n_in,
                              void* d_out, int out_size)
{
    (void)in_sizes; (void)n_in; (void)out_size;
    const float* x   = (const float*)d_in[0];
    const float* Wf  = (const float*)d_in[1];
    const float* bf  = (const float*)d_in[2];
    const float* thf = (const float*)d_in[3];
    const float* Wi  = (const float*)d_in[4];
    const float* bi  = (const float*)d_in[5];
    const float* thi = (const float*)d_in[6];
    const float* Wu  = (const float*)d_in[7];
    const float* bu  = (const float*)d_in[8];
    const float* thu = (const float*)d_in[9];
    const float* Wo  = (const float*)d_in[10];
    const float* bo  = (const float*)d_in[11];
    const float* tho = (const float*)d_in[12];
    float* out = (float*)d_out;

    proj_kernel<<<(T_STEPS * BATCH) / TILE_ROWS, PROJ_THREADS>>>(
        x, Wf, bf, thf, Wi, bi, thi, Wu, bu, thu, Wo, bo, tho);
    recur_kernel<<<BATCH / 8, 32>>>(Wf, Wi, Wu, Wo, out);
}